// round 15
// baseline (speedup 1.0000x reference)
#include <cuda_runtime.h>

// FeatureSim: attn[b,i,j] = softmax_j( sum_k w[k]*|x[b,i,k]-x[b,j,k]| ), mask j < len[b].
// B=8, L=1024, F=16 (first 11 used), out f32 [8,1024,1024].
//
// R15: R13 (19.0us, best) + BQ=16 in two 8-row chunks.
//      Per-block key load (12 LDG.128 x 16 wf = 192 wf/warp) is independent of
//      rows/block; doubling rows halves its amortized cost and all prologue
//      overhead, without R14's transpose-kernel/launch tax (which cost more
//      than its main-kernel win). e-slab stays 32KB: chunk 0 (rows 0..7)
//      compute -> barrier -> fused epilogue -> barrier -> chunk 1 (rows 8..15).
//      Unchanged: strided 4-col ownership (64B lane stride keys), scalar
//      FADD/FFMA core (free |.|/-), ex2.approx, -1e30 mask bias, warp-per-row
//      fused reduce+normalize epilogue, 3 blocks/SM.

#define L_SEQ 1024
#define FDIM  16
#define NF    11
#define BQ    16            // rows per block (2 chunks of 8)
#define CH    8             // rows per chunk == warps per block
#define TPB   256
#define BPB   (L_SEQ / BQ)  // 64 blocks per batch
#define CSTRIDE (L_SEQ / 4) // 256: column stride between a thread's 4 cols

__device__ __forceinline__ float ex2(float a) {
    float r; asm("ex2.approx.f32 %0, %1;" : "=f"(r) : "f"(a)); return r;
}

#define LOG2E 1.4426950408889634f

__global__ __launch_bounds__(TPB, 3)
void featsim_kernel(const float* __restrict__ x,
                    const int*   __restrict__ lens,
                    const float* __restrict__ w,
                    float*       __restrict__ out)
{
    const int b    = blockIdx.x / BPB;
    const int rb   = blockIdx.x % BPB;
    const int i0   = rb * BQ;
    const int tid  = threadIdx.x;
    const int lane = tid & 31;
    const int warp = tid >> 5;          // 0..7; warp w owns chunk-row w in epilogue

    __shared__ __align__(16) float sq[BQ][12];      // raw queries (11 used, pad 0)
    __shared__ __align__(16) float se[CH][L_SEQ];   // unnormalized e staging (32 KB)

    // Signed per-feature scale wl_k = w_k * log2e (|d| via free abs modifier).
    float wl[NF];
#pragma unroll
    for (int k = 0; k < NF; ++k) wl[k] = w[k] * LOG2E;

    // Stage raw queries (16 rows x 12).
    if (tid < BQ * 12) {
        int r = tid / 12, k = tid - r * 12;
        sq[r][k] = (k < NF) ? x[(size_t)(b * L_SEQ + i0 + r) * FDIM + k] : 0.f;
    }

    // Keys: 4 STRIDED cols (tid + 256*cc); 64B lane stride -> 16 wf per LDG.128,
    // loaded ONCE per block and reused for all 16 rows.
    float kk[4][NF];
#pragma unroll
    for (int cc = 0; cc < 4; ++cc) {
        const float4* kp = reinterpret_cast<const float4*>(
            x + (size_t)(b * L_SEQ + tid + CSTRIDE * cc) * FDIM);
        float4 a = kp[0], c = kp[1], d = kp[2];
        kk[cc][0] = a.x;  kk[cc][1] = a.y;  kk[cc][2]  = a.z;  kk[cc][3] = a.w;
        kk[cc][4] = c.x;  kk[cc][5] = c.y;  kk[cc][6]  = c.z;  kk[cc][7] = c.w;
        kk[cc][8] = d.x;  kk[cc][9] = d.y;  kk[cc][10] = d.z;
    }

    // Key-mask as accumulator bias: invalid col -> -1e30 -> ex2 -> exact 0.
    const int len = lens[b];
    float bias[4];
#pragma unroll
    for (int cc = 0; cc < 4; ++cc)
        bias[cc] = (tid + CSTRIDE * cc < len) ? 0.f : -1e30f;

    __syncthreads();

#pragma unroll
    for (int c = 0; c < 2; ++c) {
        if (c) __syncthreads();         // protect se reuse (epilogue reads done)

        // ---- compute chunk: 3 LDS.128/row + 88 FADD/FFMA + 4 ex2 + 4 STS.32 ----
#pragma unroll
        for (int r = 0; r < CH; ++r) {
            const float4* qp = reinterpret_cast<const float4*>(sq[c * CH + r]);
            float4 qa = qp[0];          // features 0..3
            float4 qb = qp[1];          // features 4..7
            float4 qc = qp[2];          // features 8..10 (+pad)
            const float qs[NF] = { qa.x, qa.y, qa.z, qa.w,
                                   qb.x, qb.y, qb.z, qb.w,
                                   qc.x, qc.y, qc.z };

            float s0 = bias[0], s1 = bias[1], s2 = bias[2], s3 = bias[3];
#pragma unroll
            for (int k = 0; k < NF; ++k) {
                const float q = qs[k], wk = wl[k];
                s0 = fmaf(fabsf(q - kk[0][k]), wk, s0);
                s1 = fmaf(fabsf(q - kk[1][k]), wk, s1);
                s2 = fmaf(fabsf(q - kk[2][k]), wk, s2);
                s3 = fmaf(fabsf(q - kk[3][k]), wk, s3);
            }

            se[r][tid + 0 * CSTRIDE] = ex2(s0);
            se[r][tid + 1 * CSTRIDE] = ex2(s1);
            se[r][tid + 2 * CSTRIDE] = ex2(s2);
            se[r][tid + 3 * CSTRIDE] = ex2(s3);
        }
        __syncthreads();

        // ---- fused reduce + normalize + store: warp w owns chunk-row w ----
        {
            float4 v[8];
            float acc = 0.f;
#pragma unroll
            for (int p = 0; p < 8; ++p) {
                v[p] = *reinterpret_cast<float4*>(&se[warp][lane * 4 + p * 128]);
                acc += (v[p].x + v[p].y) + (v[p].z + v[p].w);
            }
#pragma unroll
            for (int o = 16; o > 0; o >>= 1)
                acc += __shfl_xor_sync(0xffffffffu, acc, o);

            float inv; asm("rcp.approx.f32 %0, %1;" : "=f"(inv) : "f"(acc)); // len>=1 => acc>0

            float4* orow = reinterpret_cast<float4*>(
                out + (size_t)(b * L_SEQ + i0 + c * CH + warp) * L_SEQ);
#pragma unroll
            for (int p = 0; p < 8; ++p) {
                orow[p * 32 + lane] =
                    make_float4(v[p].x * inv, v[p].y * inv, v[p].z * inv, v[p].w * inv);
            }
        }
    }
}

extern "C" void kernel_launch(void* const* d_in, const int* in_sizes, int n_in,
                              void* d_out, int out_size)
{
    const float* x    = (const float*)d_in[0];   // [8,1024,16] f32
    const int*   lens = (const int*)d_in[1];     // [8] i32
    const float* w    = (const float*)d_in[2];   // [11] f32
    float*       out  = (float*)d_out;           // [8,1024,1024] f32

    dim3 grid(8 * BPB);   // 512 blocks
    dim3 block(TPB);
    featsim_kernel<<<grid, block>>>(x, lens, w, out);
}

// round 16
// speedup vs baseline: 1.0153x; 1.0153x over previous
#include <cuda_runtime.h>

// FeatureSim: attn[b,i,j] = softmax_j( sum_k w[k]*|x[b,i,k]-x[b,j,k]| ), mask j < len[b].
// B=8, L=1024, F=16 (first 11 used), out f32 [8,1024,1024].
//
// R16: static persistent schedule. R15 proved key-amortization works (L1 50.7->36.6)
//      but lost to schedule quantization (coarse 512-block grid -> 8 chunk-units max
//      per SM vs 7). Fix: grid = 444 co-resident blocks (3/SM), each owning a
//      CONTIGUOUS run of 2-3 8-row tiles: [bid*1024/444, (bid+1)*1024/444).
//      Keys (44 regs) + bias reload only on batch change (~7 of 444 blocks);
//      per-SM key wavefronts drop 7x1536 -> ~3x1536. Heavy (3-tile) blocks land
//      at most one per SM (phase spacing 0.34 > heavy window 0.31) -> makespan
//      <= 7 tiles, same as ideal. 3 barriers per tile.
//      Core & epilogue unchanged from R13: strided 4-col ownership, scalar
//      FADD/FFMA (free |.|/-), ex2.approx, -1e30 mask bias, e-slab once,
//      fused warp-per-row reduce+normalize.

#define L_SEQ 1024
#define FDIM  16
#define NF    11
#define BQ    8              // rows per tile == warps per block
#define TPB   256
#define NTILES (8 * (L_SEQ / BQ))   // 1024 tiles total
#define GRID  444            // 3 blocks/SM, co-resident on 148- or 152-SM parts
#define CSTRIDE (L_SEQ / 4)  // 256: column stride between a thread's 4 cols

__device__ __forceinline__ float ex2(float a) {
    float r; asm("ex2.approx.f32 %0, %1;" : "=f"(r) : "f"(a)); return r;
}

#define LOG2E 1.4426950408889634f

__global__ __launch_bounds__(TPB, 3)
void featsim_kernel(const float* __restrict__ x,
                    const int*   __restrict__ lens,
                    const float* __restrict__ w,
                    float*       __restrict__ out)
{
    const int tid  = threadIdx.x;
    const int lane = tid & 31;
    const int warp = tid >> 5;          // 0..7; warp w owns tile-row w in epilogue

    __shared__ __align__(16) float sq[BQ][12];      // raw queries (11 used, pad 0)
    __shared__ __align__(16) float se[BQ][L_SEQ];   // unnormalized e staging (32 KB)

    // Signed per-feature scale wl_k = w_k * log2e (|d| via free abs modifier).
    float wl[NF];
#pragma unroll
    for (int k = 0; k < NF; ++k) wl[k] = w[k] * LOG2E;

    const int start = (blockIdx.x * NTILES) / GRID;
    const int stop  = ((blockIdx.x + 1) * NTILES) / GRID;

    int   cur_b = -1;
    float kk[4][NF];
    float bias[4];

    for (int t = start; t < stop; ++t) {
        const int b  = t >> 7;          // tile t -> batch
        const int i0 = (t & 127) * BQ;  // first row of tile

        // Stage this tile's queries (96 scalar LDG, tiny).
        if (tid < BQ * 12) {
            int r = tid / 12, k = tid - r * 12;
            sq[r][k] = (k < NF) ? x[(size_t)(b * L_SEQ + i0 + r) * FDIM + k] : 0.f;
        }

        // Keys + mask bias: reload only when the batch changes (block-uniform).
        if (b != cur_b) {
            cur_b = b;
#pragma unroll
            for (int cc = 0; cc < 4; ++cc) {
                const float4* kp = reinterpret_cast<const float4*>(
                    x + (size_t)(b * L_SEQ + tid + CSTRIDE * cc) * FDIM);
                float4 a = kp[0], c = kp[1], d = kp[2];
                kk[cc][0] = a.x;  kk[cc][1] = a.y;  kk[cc][2]  = a.z;  kk[cc][3] = a.w;
                kk[cc][4] = c.x;  kk[cc][5] = c.y;  kk[cc][6]  = c.z;  kk[cc][7] = c.w;
                kk[cc][8] = d.x;  kk[cc][9] = d.y;  kk[cc][10] = d.z;
            }
            const int len = lens[b];
#pragma unroll
            for (int cc = 0; cc < 4; ++cc)
                bias[cc] = (tid + CSTRIDE * cc < len) ? 0.f : -1e30f;  // -> ex2 -> exact 0
        }
        __syncthreads();

        // ---- compute: 3 LDS.128/row + 88 FADD/FFMA + 4 ex2 + 4 STS.32 ----
#pragma unroll
        for (int r = 0; r < BQ; ++r) {
            const float4* qp = reinterpret_cast<const float4*>(sq[r]);
            float4 qa = qp[0];          // features 0..3
            float4 qb = qp[1];          // features 4..7
            float4 qc = qp[2];          // features 8..10 (+pad)
            const float qs[NF] = { qa.x, qa.y, qa.z, qa.w,
                                   qb.x, qb.y, qb.z, qb.w,
                                   qc.x, qc.y, qc.z };

            float s0 = bias[0], s1 = bias[1], s2 = bias[2], s3 = bias[3];
#pragma unroll
            for (int k = 0; k < NF; ++k) {
                const float q = qs[k], wk = wl[k];
                s0 = fmaf(fabsf(q - kk[0][k]), wk, s0);
                s1 = fmaf(fabsf(q - kk[1][k]), wk, s1);
                s2 = fmaf(fabsf(q - kk[2][k]), wk, s2);
                s3 = fmaf(fabsf(q - kk[3][k]), wk, s3);
            }

            se[r][tid + 0 * CSTRIDE] = ex2(s0);
            se[r][tid + 1 * CSTRIDE] = ex2(s1);
            se[r][tid + 2 * CSTRIDE] = ex2(s2);
            se[r][tid + 3 * CSTRIDE] = ex2(s3);
        }
        __syncthreads();

        // ---- fused reduce + normalize + store: warp w owns tile-row w ----
        {
            float4 v[8];
            float acc = 0.f;
#pragma unroll
            for (int p = 0; p < 8; ++p) {
                v[p] = *reinterpret_cast<float4*>(&se[warp][lane * 4 + p * 128]);
                acc += (v[p].x + v[p].y) + (v[p].z + v[p].w);
            }
#pragma unroll
            for (int o = 16; o > 0; o >>= 1)
                acc += __shfl_xor_sync(0xffffffffu, acc, o);

            float inv; asm("rcp.approx.f32 %0, %1;" : "=f"(inv) : "f"(acc)); // len>=1 => acc>0

            float4* orow = reinterpret_cast<float4*>(
                out + (size_t)(b * L_SEQ + i0 + warp) * L_SEQ);
#pragma unroll
            for (int p = 0; p < 8; ++p) {
                orow[p * 32 + lane] =
                    make_float4(v[p].x * inv, v[p].y * inv, v[p].z * inv, v[p].w * inv);
            }
        }
        __syncthreads();   // se/sq safe to overwrite next tile
    }
}

extern "C" void kernel_launch(void* const* d_in, const int* in_sizes, int n_in,
                              void* d_out, int out_size)
{
    const float* x    = (const float*)d_in[0];   // [8,1024,16] f32
    const int*   lens = (const int*)d_in[1];     // [8] i32
    const float* w    = (const float*)d_in[2];   // [11] f32
    float*       out  = (float*)d_out;           // [8,1024,1024] f32

    featsim_kernel<<<GRID, TPB>>>(x, lens, w, out);
}

// round 17
// speedup vs baseline: 1.1252x; 1.1083x over previous
#include <cuda_runtime.h>

// FeatureSim: attn[b,i,j] = softmax_j( sum_k w[k]*|x[b,i,k]-x[b,j,k]| ), mask j < len[b].
// B=8, L=1024, F=16 (first 11 used), out f32 [8,1024,1024].
//
// R17: R14's main kernel (16.86us measured — best main by far, coalesced feature-major
//      key loads from a transposed copy) + a WIDE transpose prologue.
//      R14's loss was the prologue: 32 blocks on 148 SMs = latency-bound ~1.6us
//      + inter-kernel gap. Now 256 blocks x 128 threads (32 rows each): one
//      coalesced LDG.128 + ~3 coalesced STG.32 per thread through a padded smem
//      tile -> sub-microsecond.
//      Main kernel unchanged: strided 4-col ownership, keys from g_xT (4B lane
//      stride -> 1 wf per LDG), scalar FADD/FFMA core (free |.|/-), ex2.approx,
//      -1e30 mask bias, e-slab once, fused warp-per-row epilogue, 2 barriers,
//      3 blocks/SM.

#define L_SEQ 1024
#define FDIM  16
#define NF    11
#define BQ    8             // rows per block == warps per block
#define TPB   256
#define BPB   (L_SEQ / BQ)  // 128 blocks per batch
#define CSTRIDE (L_SEQ / 4) // 256: column stride between a thread's 4 cols

__device__ float g_xT[8][12][L_SEQ];   // feature-major copy of x (k<11 used), 384KB

__device__ __forceinline__ float ex2(float a) {
    float r; asm("ex2.approx.f32 %0, %1;" : "=f"(r) : "f"(a)); return r;
}

#define LOG2E 1.4426950408889634f

// ---------------- Prologue: x[b][j][k] -> g_xT[b][k][j], 256 wide blocks --------
__global__ __launch_bounds__(128)
void transpose_kernel(const float* __restrict__ x)
{
    const int b     = blockIdx.x >> 5;          // 0..7
    const int chunk = blockIdx.x & 31;          // 0..31, 32 rows each
    const int t     = threadIdx.x;

    __shared__ float ts[32][17];                // pad 17: conflict-free both phases

    // Load 32 rows x 16 floats = 128 float4, one coalesced LDG.128 per thread.
    const float4* xb = reinterpret_cast<const float4*>(
        x + (size_t)(b * L_SEQ + chunk * 32) * FDIM);
    {
        int row = t >> 2, quad = t & 3;
        float4 v = xb[t];
        ts[row][quad * 4 + 0] = v.x;
        ts[row][quad * 4 + 1] = v.y;
        ts[row][quad * 4 + 2] = v.z;
        ts[row][quad * 4 + 3] = v.w;
    }
    __syncthreads();

    // Write k-major: 352 scalar stores, 128B-coalesced per k-group.
    for (int i = t; i < NF * 32; i += 128) {
        int k = i >> 5, j = i & 31;
        g_xT[b][k][chunk * 32 + j] = ts[j][k];
    }
}

// ---------------- Main kernel (identical to R14) ----------------
__global__ __launch_bounds__(TPB, 3)
void featsim_kernel(const float* __restrict__ x,
                    const int*   __restrict__ lens,
                    const float* __restrict__ w,
                    float*       __restrict__ out)
{
    const int b    = blockIdx.x / BPB;
    const int rb   = blockIdx.x % BPB;
    const int i0   = rb * BQ;
    const int tid  = threadIdx.x;
    const int lane = tid & 31;
    const int warp = tid >> 5;          // 0..7; warp w owns row w in the epilogue

    __shared__ __align__(16) float sq[BQ][12];      // raw queries (11 used, pad 0)
    __shared__ __align__(16) float se[BQ][L_SEQ];   // unnormalized e staging (32 KB)

    // Signed per-feature scale wl_k = w_k * log2e (|d| via free abs modifier).
    float wl[NF];
#pragma unroll
    for (int k = 0; k < NF; ++k) wl[k] = w[k] * LOG2E;

    // Stage raw queries (from row-major x; tiny).
    if (tid < BQ * 12) {
        int r = tid / 12, k = tid - r * 12;
        sq[r][k] = (k < NF) ? x[(size_t)(b * L_SEQ + i0 + r) * FDIM + k] : 0.f;
    }

    // Keys from feature-major xT: lane stride 4B -> every LDG is 1 wavefront.
    float kk[4][NF];
#pragma unroll
    for (int k = 0; k < NF; ++k) {
        const float* kp = &g_xT[b][k][tid];
#pragma unroll
        for (int cc = 0; cc < 4; ++cc)
            kk[cc][k] = kp[cc * CSTRIDE];
    }

    // Key-mask as accumulator bias: invalid col -> -1e30 -> ex2 -> exact 0.
    const int len = lens[b];
    float bias[4];
#pragma unroll
    for (int cc = 0; cc < 4; ++cc)
        bias[cc] = (tid + CSTRIDE * cc < len) ? 0.f : -1e30f;

    __syncthreads();

    // ---- compute: 3 LDS.128/row + 88 FADD/FFMA + 4 ex2 + 4 STS.32 ----
#pragma unroll
    for (int r = 0; r < BQ; ++r) {
        const float4* qp = reinterpret_cast<const float4*>(sq[r]);
        float4 qa = qp[0];              // features 0..3
        float4 qb = qp[1];              // features 4..7
        float4 qc = qp[2];              // features 8..10 (+pad)
        const float qs[NF] = { qa.x, qa.y, qa.z, qa.w,
                               qb.x, qb.y, qb.z, qb.w,
                               qc.x, qc.y, qc.z };

        float s0 = bias[0], s1 = bias[1], s2 = bias[2], s3 = bias[3];
#pragma unroll
        for (int k = 0; k < NF; ++k) {
            const float q = qs[k], wk = wl[k];
            s0 = fmaf(fabsf(q - kk[0][k]), wk, s0);
            s1 = fmaf(fabsf(q - kk[1][k]), wk, s1);
            s2 = fmaf(fabsf(q - kk[2][k]), wk, s2);
            s3 = fmaf(fabsf(q - kk[3][k]), wk, s3);
        }

        se[r][tid + 0 * CSTRIDE] = ex2(s0);
        se[r][tid + 1 * CSTRIDE] = ex2(s1);
        se[r][tid + 2 * CSTRIDE] = ex2(s2);
        se[r][tid + 3 * CSTRIDE] = ex2(s3);
    }
    __syncthreads();

    // ---- fused reduce + normalize + store: warp w owns row w ----
    {
        float4 v[8];
        float acc = 0.f;
#pragma unroll
        for (int p = 0; p < 8; ++p) {
            v[p] = *reinterpret_cast<float4*>(&se[warp][lane * 4 + p * 128]);
            acc += (v[p].x + v[p].y) + (v[p].z + v[p].w);
        }
#pragma unroll
        for (int o = 16; o > 0; o >>= 1)
            acc += __shfl_xor_sync(0xffffffffu, acc, o);

        float inv; asm("rcp.approx.f32 %0, %1;" : "=f"(inv) : "f"(acc));  // len>=1 => acc>0

        float4* orow = reinterpret_cast<float4*>(
            out + (size_t)(b * L_SEQ + i0 + warp) * L_SEQ);
#pragma unroll
        for (int p = 0; p < 8; ++p) {
            orow[p * 32 + lane] =
                make_float4(v[p].x * inv, v[p].y * inv, v[p].z * inv, v[p].w * inv);
        }
    }
}

extern "C" void kernel_launch(void* const* d_in, const int* in_sizes, int n_in,
                              void* d_out, int out_size)
{
    const float* x    = (const float*)d_in[0];   // [8,1024,16] f32
    const int*   lens = (const int*)d_in[1];     // [8] i32
    const float* w    = (const float*)d_in[2];   // [11] f32
    float*       out  = (float*)d_out;           // [8,1024,1024] f32

    transpose_kernel<<<256, 128>>>(x);           // x -> g_xT (feature-major), wide & short
    featsim_kernel<<<8 * BPB, TPB>>>(x, lens, w, out);   // 1024 blocks
}